// round 10
// baseline (speedup 1.0000x reference)
#include <cuda_runtime.h>
#include <cuda_bf16.h>

// Fixed shapes from reference setup_inputs
#define NPTS 8192
#define TPB  256
#define TILE 256                     // i-tile edge (TPB * 1 i per thread)
#define JC   128                     // j-chunk per CTA
#define NTILES (NPTS / TILE)         // 32
#define NTRI (NTILES * (NTILES + 1) / 2)   // 528 triangular tiles
#define NBLK (NTRI * 2)              // 1056 CTAs (2 j-chunks per tile)

#define NBINS 4096                   // 12-bit Morton (4 bits/axis), 2.5-unit cells
#define NSB   8                      // superblocks of 1024 points

// Sorted copies + metadata (no device allocation; fixed globals)
__device__ float g_sx[NPTS], g_sy[NPTS], g_sz[NPTS], g_ss[NPTS];
__device__ float g_q0[NPTS], g_q1[NPTS], g_q2[NPTS], g_q3[NPTS];
__device__ unsigned g_bin[NPTS];
__device__ unsigned g_bh[NBINS * NSB];      // bin-major histograms (self-cleaning)
__device__ unsigned g_bstart[NBINS * NSB];  // per-(bin,superblock) start
__device__ float g_partials[NBLK];
__device__ unsigned int g_count;            // zero at load; self-reset each launch

// A&S 7.1.25 (3-term, |eps| <= 2.5e-5), x = r/sqrt(2) folded into p
#define P3S  0.3326701f              // 0.47047 / sqrt(2)
#define A1c  0.3480242f
#define A2c  (-0.0958798f)
#define A3c  0.7478556f
#define NEG_HALF_LOG2E (-0.7213475204444817f)
#define SELF_RATIO 0.7978845608028654f   // (1/(2pi)^1.5) / (1/(4pi))
#define NEAR_R2 9.0f                 // r=3: erfc(2.12)~2.7e-3, incoherent -> safe

__device__ __forceinline__ float rsqf(float a) {
    float r; asm("rsqrt.approx.f32 %0,%1;" : "=f"(r) : "f"(a)); return r;
}
__device__ __forceinline__ float rcpf(float a) {
    float r; asm("rcp.approx.f32 %0,%1;" : "=f"(r) : "f"(a)); return r;
}
__device__ __forceinline__ float exf(float a) {
    float r; asm("ex2.approx.f32 %0,%1;" : "=f"(r) : "f"(a)); return r;
}
// Near-field kernel value erf(r/sqrt2)/r given r2 and rv = rsqrt(r2).
__device__ __forceinline__ float kern_corr(float r2, float rv) {
    const float r  = r2 * rv;
    const float tt = rcpf(fmaf(P3S, r, 1.0f));            // MUFU.RCP
    float h = fmaf(A3c, tt, A2c);
    h = fmaf(h, tt, A1c);
    const float u = (h * tt) * exf(r2 * NEG_HALF_LOG2E);  // MUFU.EX2
    return fmaf(-u, rv, rv);                              // (1 - poly*exp) * rv
}

// ---------- K1: Morton bin + bin-major histogram ----------
__device__ __forceinline__ unsigned spread4(unsigned v) {
    return (v & 1u) | ((v & 2u) << 2) | ((v & 4u) << 4) | ((v & 8u) << 6);
}
__global__ void bin_hist_kernel(const float* __restrict__ pos) {
    const int i = blockIdx.x * blockDim.x + threadIdx.x;
    const float x = pos[3 * i + 0];
    const float y = pos[3 * i + 1];
    const float z = pos[3 * i + 2];
    const unsigned ux = (unsigned)fminf(fmaxf((x + 20.f) * 0.4f, 0.f), 15.f);
    const unsigned uy = (unsigned)fminf(fmaxf((y + 20.f) * 0.4f, 0.f), 15.f);
    const unsigned uz = (unsigned)fminf(fmaxf((z + 20.f) * 0.4f, 0.f), 15.f);
    const unsigned b = (spread4(ux) << 2) | (spread4(uy) << 1) | spread4(uz);
    g_bin[i] = b;
    atomicAdd(&g_bh[b * NSB + (i >> 10)], 1u);   // counts: order-independent
    if (i == 0) g_count = 0;                      // belt & braces for replay
}

// ---------- K2: fused totals + scan + column starts (one CTA, 1024 thr) ----------
__global__ void __launch_bounds__(1024)
scan_colstart_kernel() {
    const int t = threadIdx.x;                   // 4 bins per thread
    unsigned cnt[4][NSB];
    unsigned tot[4];
#pragma unroll
    for (int k = 0; k < 4; k++) {
        const int b = t * 4 + k;
        const uint4 lo = *(const uint4*)&g_bh[b * NSB + 0];
        const uint4 hi = *(const uint4*)&g_bh[b * NSB + 4];
        cnt[k][0] = lo.x; cnt[k][1] = lo.y; cnt[k][2] = lo.z; cnt[k][3] = lo.w;
        cnt[k][4] = hi.x; cnt[k][5] = hi.y; cnt[k][6] = hi.z; cnt[k][7] = hi.w;
        tot[k] = ((lo.x + lo.y) + (lo.z + lo.w)) + ((hi.x + hi.y) + (hi.z + hi.w));
    }
    // local exclusive prefix over this thread's 4 bins
    unsigned lpre[4];
    lpre[0] = 0;
    lpre[1] = tot[0];
    lpre[2] = tot[0] + tot[1];
    lpre[3] = tot[0] + tot[1] + tot[2];
    __shared__ unsigned ssum[1024];
    ssum[t] = lpre[3] + tot[3];
    __syncthreads();
    // inclusive Hillis-Steele over 1024 thread-sums
    for (int o = 1; o < 1024; o <<= 1) {
        const unsigned v = (t >= o) ? ssum[t - o] : 0u;
        __syncthreads();
        ssum[t] += v;
        __syncthreads();
    }
    const unsigned base = (t > 0) ? ssum[t - 1] : 0u;
#pragma unroll
    for (int k = 0; k < 4; k++) {
        const int b = t * 4 + k;
        unsigned run = base + lpre[k];
#pragma unroll
        for (int m = 0; m < NSB; m++) {
            g_bstart[b * NSB + m] = run;
            run += cnt[k][m];
            g_bh[b * NSB + m] = 0;               // clean for next graph replay
        }
    }
}

// ---------- K3: stable rank + gather into sorted SoA (8 CTAs x 1024) ----------
__global__ void __launch_bounds__(1024)
gather_kernel(const float* __restrict__ pos, const float* __restrict__ q) {
    __shared__ unsigned sbin[1024];
    const int t = threadIdx.x;
    const int i = blockIdx.x * 1024 + t;
    const unsigned b = g_bin[i];
    sbin[t] = b;
    __syncthreads();
    unsigned off = 0;
#pragma unroll 16
    for (int j = 0; j < 1024; j++)
        off += (sbin[j] == b) && (j < t);         // stable within superblock
    const unsigned r = g_bstart[b * NSB + blockIdx.x] + off;
    const float x = pos[3 * i + 0];
    const float y = pos[3 * i + 1];
    const float z = pos[3 * i + 2];
    g_sx[r] = x; g_sy[r] = y; g_sz[r] = z;
    g_ss[r] = fmaf(x, x, fmaf(y, y, z * z));
    g_q0[r] = q[4 * i + 0];
    g_q1[r] = q[4 * i + 1];
    g_q2[r] = q[4 * i + 2];
    g_q3[r] = q[4 * i + 3];
}

// ---------- Main pair kernel (sorted data, far-field vote-skip) ----------
__global__ void __launch_bounds__(TPB, 4)
ewald_pair_kernel(float* __restrict__ out) {
    __shared__ float4 sp[JC];   // {x, y, z, |p|^2}
    __shared__ float4 sb[JC];   // {b0, b1, b2, b3}

    const int t = threadIdx.x;
    const int tile  = blockIdx.x >> 1;
    const int chunk = blockIdx.x & 1;
    int I = 0, rem = tile;
    while (rem >= NTILES - I) { rem -= NTILES - I; I++; }
    const int J = I + rem;
    const bool diag = (I == J);

    const int jbase = J * TILE + chunk * JC;
    if (t < JC) {
        const int j = jbase + t;
        sp[t] = make_float4(g_sx[j], g_sy[j], g_sz[j], g_ss[j]);
    } else {
        const int tq = t - JC, j = jbase + tq;
        sb[tq] = make_float4(g_q0[j], g_q1[j], g_q2[j], g_q3[j]);
    }
    __syncthreads();

    const int i0 = I * TILE + t;           // one i per thread (small warp blob)
    const float xi = g_sx[i0], yi = g_sy[i0], zi = g_sz[i0];

    float acc0 = 0.f, acc1 = 0.f, acc2 = 0.f, acc3 = 0.f;

    if (!diag) {
        // dot-form r^2 = (si + sj) - 2 pi.pj
        const float nx2 = -2.f * xi, ny2 = -2.f * yi, nz2 = -2.f * zi;
        const float si  = g_ss[i0];
#pragma unroll 8
        for (int jj = 0; jj < JC; jj++) {
            const float4 p = sp[jj];
            const float r2 = fmaf(p.x, nx2, fmaf(p.y, ny2, fmaf(p.z, nz2, p.w + si)));
            const float rv = rsqf(r2);
            float k = rv;                                   // far field: erf == 1
            if (__any_sync(0xffffffffu, r2 < NEAR_R2))
                k = kern_corr(r2, rv);                      // also valid when far
            const float4 b = sb[jj];
            acc0 = fmaf(k, b.x, acc0);
            acc1 = fmaf(k, b.y, acc1);
            acc2 = fmaf(k, b.z, acc2);
            acc3 = fmaf(k, b.w, acc3);
        }
    } else {
        // exact diff-form r^2 so the diagonal is exactly zero for the select
#pragma unroll 8
        for (int jj = 0; jj < JC; jj++) {
            const float4 p = sp[jj];
            const float dx = p.x - xi;
            const float dy = p.y - yi;
            const float dz = p.z - zi;
            const float r2 = fmaf(dx, dx, fmaf(dy, dy, dz * dz));
            const float rv = rsqf(r2);
            float k = rv;
            if (__any_sync(0xffffffffu, r2 < NEAR_R2))
                k = kern_corr(r2, rv);
            k = (r2 > 0.f) ? k : 0.f;                       // exact-zero diagonal
            const float4 b = sb[jj];
            acc0 = fmaf(k, b.x, acc0);
            acc1 = fmaf(k, b.y, acc1);
            acc2 = fmaf(k, b.z, acc2);
            acc3 = fmaf(k, b.w, acc3);
        }
    }

    // dot with i charges (L1/L2 hit)
    const float a0 = g_q0[i0], a1 = g_q1[i0], a2 = g_q2[i0], a3 = g_q3[i0];
    float s = fmaf(a0, acc0, fmaf(a1, acc1, fmaf(a2, acc2, a3 * acc3)));
    if (!diag) s = s + s;
    else if (chunk == 0) {
        const float qq = fmaf(a0, a0, fmaf(a1, a1, fmaf(a2, a2, a3 * a3)));
        s = fmaf(SELF_RATIO, qq, s);
    }

    // deterministic in-block reduction (8 warps)
#pragma unroll
    for (int o = 16; o > 0; o >>= 1)
        s += __shfl_down_sync(0xffffffffu, s, o);

    __shared__ float red[TPB / 32];
    if ((t & 31) == 0) red[t >> 5] = s;
    __syncthreads();

    __shared__ bool is_last;
    if (t == 0) {
        g_partials[blockIdx.x] = ((red[0] + red[1]) + (red[2] + red[3]))
                               + ((red[4] + red[5]) + (red[6] + red[7]));
        __threadfence();
        const unsigned int c = atomicAdd(&g_count, 1u);
        is_last = (c == NBLK - 1);
    }
    __syncthreads();

    if (is_last) {
        __threadfence();
        double d = 0.0;
        for (int u = t; u < NBLK; u += TPB) d += (double)g_partials[u];

        __shared__ double rs[TPB];
        rs[t] = d;
        __syncthreads();
#pragma unroll
        for (int o = TPB / 2; o > 0; o >>= 1) {
            if (t < o) rs[t] += rs[t + o];
            __syncthreads();
        }
        if (t == 0) {
            const double INV_4PI = 0.07957747154594767;
            out[0] = (float)(rs[0] * INV_4PI);
            g_count = 0;   // reset for next graph replay
        }
    }
}

extern "C" void kernel_launch(void* const* d_in, const int* in_sizes, int n_in,
                              void* d_out, int out_size) {
    const float* pos = (const float*)d_in[0];   // [8192,3] fp32
    const float* q   = (const float*)d_in[1];   // [8192,4] fp32
    float* out = (float*)d_out;                 // [1] fp32

    bin_hist_kernel<<<NPTS / 256, 256>>>(pos);
    scan_colstart_kernel<<<1, 1024>>>();
    gather_kernel<<<NPTS / 1024, 1024>>>(pos, q);
    ewald_pair_kernel<<<NBLK, TPB>>>(out);
}

// round 11
// speedup vs baseline: 1.3285x; 1.3285x over previous
#include <cuda_runtime.h>
#include <cuda_bf16.h>

// Fixed shapes from reference setup_inputs
#define NPTS 8192
#define TPB  256
#define TILE 256                     // i-tile edge (1 i per thread)
#define JC   128                     // j-chunk per CTA
#define NTILES (NPTS / TILE)         // 32
#define NTRI (NTILES * (NTILES + 1) / 2)   // 528 triangular tiles
#define NBLK (NTRI * 2)              // 1056 CTAs

#define NBINS 4096                   // 12-bit Morton (4 bits/axis), 2.5-unit cells
#define NSB   32                     // superblocks of 256 points

// Sorted copies + metadata (no device allocation; fixed globals)
__device__ float g_sx[NPTS], g_sy[NPTS], g_sz[NPTS], g_ss[NPTS];
__device__ float g_q0[NPTS], g_q1[NPTS], g_q2[NPTS], g_q3[NPTS];
__device__ unsigned g_bin[NPTS];
__device__ unsigned g_bh[NBINS * NSB];      // bin-major histograms (self-cleaning)
__device__ unsigned g_tot[NBINS];
__device__ unsigned g_binstart[NBINS];
__device__ unsigned g_bstart[NBINS * NSB];
__device__ float g_partials[NBLK];
__device__ unsigned int g_count;            // zero at load; self-reset each launch

// A&S 7.1.25 (3-term, |eps| <= 2.5e-5), x = r/sqrt(2) folded into p
#define P3S  0.3326701f              // 0.47047 / sqrt(2)
#define A1c  0.3480242f
#define A2c  (-0.0958798f)
#define A3c  0.7478556f
#define NEG_HALF_LOG2E (-0.7213475204444817f)
#define SELF_RATIO 0.7978845608028654f   // (1/(2pi)^1.5) / (1/(4pi))
#define NEAR_R  3.0f                 // erfc(3/sqrt2) ~ 2.7e-3, incoherent -> safe
#define NEAR_R2 9.0f

__device__ __forceinline__ float rsqf(float a) {
    float r; asm("rsqrt.approx.f32 %0,%1;" : "=f"(r) : "f"(a)); return r;
}
__device__ __forceinline__ float rcpf(float a) {
    float r; asm("rcp.approx.f32 %0,%1;" : "=f"(r) : "f"(a)); return r;
}
__device__ __forceinline__ float exf(float a) {
    float r; asm("ex2.approx.f32 %0,%1;" : "=f"(r) : "f"(a)); return r;
}
// Full near-field kernel value erf(r/sqrt2)/r.
__device__ __forceinline__ float kern_corr(float r2, float rv) {
    const float r  = r2 * rv;
    const float tt = rcpf(fmaf(P3S, r, 1.0f));
    float h = fmaf(A3c, tt, A2c);
    h = fmaf(h, tt, A1c);
    const float u = (h * tt) * exf(r2 * NEG_HALF_LOG2E);
    return fmaf(-u, rv, rv);
}
// Correction delta: kern_corr(r2) - rv = -(poly*tt*ex)*rv  (-> 0 when far)
__device__ __forceinline__ float corr_delta(float r2, float rv) {
    const float r  = r2 * rv;
    const float tt = rcpf(fmaf(P3S, r, 1.0f));
    float h = fmaf(A3c, tt, A2c);
    h = fmaf(h, tt, A1c);
    const float u = (h * tt) * exf(r2 * NEG_HALF_LOG2E);
    return -u * rv;
}

// ---------- K1: Morton bin + bin-major histogram ----------
__device__ __forceinline__ unsigned spread4(unsigned v) {
    return (v & 1u) | ((v & 2u) << 2) | ((v & 4u) << 4) | ((v & 8u) << 6);
}
__global__ void bin_hist_kernel(const float* __restrict__ pos) {
    const int i = blockIdx.x * blockDim.x + threadIdx.x;
    const float x = pos[3 * i + 0];
    const float y = pos[3 * i + 1];
    const float z = pos[3 * i + 2];
    const unsigned ux = (unsigned)fminf(fmaxf((x + 20.f) * 0.4f, 0.f), 15.f);
    const unsigned uy = (unsigned)fminf(fmaxf((y + 20.f) * 0.4f, 0.f), 15.f);
    const unsigned uz = (unsigned)fminf(fmaxf((z + 20.f) * 0.4f, 0.f), 15.f);
    const unsigned b = (spread4(ux) << 2) | (spread4(uy) << 1) | spread4(uz);
    g_bin[i] = b;
    atomicAdd(&g_bh[b * NSB + (i >> 8)], 1u);    // counts: order-independent
    if (i == 0) g_count = 0;                      // belt & braces for replay
}

// ---------- K2: bin totals (4096 threads, contiguous reads) ----------
__global__ void tot_kernel() {
    const int b = blockIdx.x * blockDim.x + threadIdx.x;
    const uint4* p = (const uint4*)&g_bh[b * NSB];
    unsigned s = 0;
#pragma unroll
    for (int k = 0; k < NSB / 4; k++) {
        const uint4 v = p[k];
        s += (v.x + v.y) + (v.z + v.w);
    }
    g_tot[b] = s;
}

// ---------- K3: exclusive scan of 4096 totals (one small CTA) ----------
__global__ void scan_kernel() {
    const int t = threadIdx.x;           // 256 threads, 16 bins each
    unsigned loc[16];
    unsigned s = 0;
#pragma unroll
    for (int k = 0; k < 16; k++) { loc[k] = s; s += g_tot[t * 16 + k]; }
    __shared__ unsigned ts[256];
    ts[t] = s;
    __syncthreads();
    if (t == 0) {
        unsigned run = 0;
        for (int u = 0; u < 256; u++) { unsigned v = ts[u]; ts[u] = run; run += v; }
    }
    __syncthreads();
    const unsigned base = ts[t];
#pragma unroll
    for (int k = 0; k < 16; k++) g_binstart[t * 16 + k] = base + loc[k];
}

// ---------- K4: per-(bin,superblock) starts (contiguous); self-clean g_bh ----------
__global__ void colstart_kernel() {
    const int b = blockIdx.x * blockDim.x + threadIdx.x;
    unsigned run = g_binstart[b];
#pragma unroll
    for (int m = 0; m < NSB; m++) {
        const unsigned c = g_bh[b * NSB + m];
        g_bstart[b * NSB + m] = run;
        run += c;
        g_bh[b * NSB + m] = 0;           // clean for next graph replay
    }
}

// ---------- K5: stable rank + gather into sorted SoA ----------
__global__ void gather_kernel(const float* __restrict__ pos, const float* __restrict__ q) {
    __shared__ unsigned sbin[256];
    const int t = threadIdx.x;
    const int i = blockIdx.x * 256 + t;
    const unsigned b = g_bin[i];
    sbin[t] = b;
    __syncthreads();
    unsigned off = 0;
#pragma unroll 8
    for (int j = 0; j < 256; j++)
        off += (sbin[j] == b) && (j < t);          // stable within superblock
    const unsigned r = g_bstart[b * NSB + blockIdx.x] + off;
    const float x = pos[3 * i + 0];
    const float y = pos[3 * i + 1];
    const float z = pos[3 * i + 2];
    g_sx[r] = x; g_sy[r] = y; g_sz[r] = z;
    g_ss[r] = fmaf(x, x, fmaf(y, y, z * z));
    g_q0[r] = q[4 * i + 0];
    g_q1[r] = q[4 * i + 1];
    g_q2[r] = q[4 * i + 2];
    g_q3[r] = q[4 * i + 3];
}

// ---------- Main pair kernel: mask-then-two-pass ----------
__global__ void __launch_bounds__(TPB, 4)
ewald_pair_kernel(float* __restrict__ out) {
    __shared__ float4 sp[JC];   // {x, y, z, |p|^2}
    __shared__ float4 sb[JC];   // {b0, b1, b2, b3}

    const int t = threadIdx.x;
    const int lane = t & 31;
    const int tile  = blockIdx.x >> 1;
    const int chunk = blockIdx.x & 1;
    int I = 0, rem = tile;
    while (rem >= NTILES - I) { rem -= NTILES - I; I++; }
    const int J = I + rem;
    const bool diag = (I == J);

    const int jbase = J * TILE + chunk * JC;
    if (t < JC) {
        const int j = jbase + t;
        sp[t] = make_float4(g_sx[j], g_sy[j], g_sz[j], g_ss[j]);
    } else {
        const int tq = t - JC, j = jbase + tq;
        sb[tq] = make_float4(g_q0[j], g_q1[j], g_q2[j], g_q3[j]);
    }
    __syncthreads();

    const int i0 = I * TILE + t;
    const float xi = g_sx[i0], yi = g_sy[i0], zi = g_sz[i0];

    float acc0 = 0.f, acc1 = 0.f, acc2 = 0.f, acc3 = 0.f;

    if (!diag) {
        // --- warp i-blob bounding sphere (once) ---
        float mnx = xi, mxx = xi, mny = yi, mxy = yi, mnz = zi, mxz = zi;
#pragma unroll
        for (int o = 16; o > 0; o >>= 1) {
            mnx = fminf(mnx, __shfl_xor_sync(0xffffffffu, mnx, o));
            mxx = fmaxf(mxx, __shfl_xor_sync(0xffffffffu, mxx, o));
            mny = fminf(mny, __shfl_xor_sync(0xffffffffu, mny, o));
            mxy = fmaxf(mxy, __shfl_xor_sync(0xffffffffu, mxy, o));
            mnz = fminf(mnz, __shfl_xor_sync(0xffffffffu, mnz, o));
            mxz = fmaxf(mxz, __shfl_xor_sync(0xffffffffu, mxz, o));
        }
        const float cx = 0.5f * (mnx + mxx);
        const float cy = 0.5f * (mny + mxy);
        const float cz = 0.5f * (mnz + mxz);
        const float hx = 0.5f * (mxx - mnx);
        const float hy = 0.5f * (mxy - mny);
        const float hz = 0.5f * (mxz - mnz);
        const float Rb = sqrtf(fmaf(hx, hx, fmaf(hy, hy, hz * hz)));
        const float th = NEAR_R + Rb + 0.05f;
        const float th2 = th * th;

        // --- near masks: each lane tests j = lane + 32k ---
        unsigned mask[4];
#pragma unroll
        for (int k = 0; k < 4; k++) {
            const float4 p = sp[k * 32 + lane];
            const float dx = p.x - cx, dy = p.y - cy, dz = p.z - cz;
            const float d2 = fmaf(dx, dx, fmaf(dy, dy, dz * dz));
            mask[k] = __ballot_sync(0xffffffffu, d2 < th2);
        }

        // --- pass 1: branchless far path for all j ---
        const float nx2 = -2.f * xi, ny2 = -2.f * yi, nz2 = -2.f * zi;
        const float si  = g_ss[i0];
#pragma unroll 8
        for (int jj = 0; jj < JC; jj++) {
            const float4 p = sp[jj];
            const float r2 = fmaf(p.x, nx2, fmaf(p.y, ny2, fmaf(p.z, nz2, p.w + si)));
            const float rv = rsqf(r2);
            const float4 b = sb[jj];
            acc0 = fmaf(rv, b.x, acc0);
            acc1 = fmaf(rv, b.y, acc1);
            acc2 = fmaf(rv, b.z, acc2);
            acc3 = fmaf(rv, b.w, acc3);
        }

        // --- pass 2: erf correction only for near j (warp-uniform bit loop) ---
#pragma unroll
        for (int k = 0; k < 4; k++) {
            unsigned m = mask[k];
            while (m) {
                const int bit = __ffs(m) - 1;
                m &= m - 1u;
                const int jj = k * 32 + bit;
                const float4 p = sp[jj];
                const float r2 = fmaf(p.x, nx2, fmaf(p.y, ny2, fmaf(p.z, nz2, p.w + si)));
                const float rv = rsqf(r2);
                const float d  = corr_delta(r2, rv);   // ~0 for genuinely-far i
                const float4 b = sb[jj];
                acc0 = fmaf(d, b.x, acc0);
                acc1 = fmaf(d, b.y, acc1);
                acc2 = fmaf(d, b.z, acc2);
                acc3 = fmaf(d, b.w, acc3);
            }
        }
    } else {
        // diagonal tile: exact diff-form + per-iter vote (64 CTAs only)
#pragma unroll 8
        for (int jj = 0; jj < JC; jj++) {
            const float4 p = sp[jj];
            const float dx = p.x - xi;
            const float dy = p.y - yi;
            const float dz = p.z - zi;
            const float r2 = fmaf(dx, dx, fmaf(dy, dy, dz * dz));
            const float rv = rsqf(r2);
            float k = rv;
            if (__any_sync(0xffffffffu, r2 < NEAR_R2))
                k = kern_corr(r2, rv);
            k = (r2 > 0.f) ? k : 0.f;                   // exact-zero diagonal
            const float4 b = sb[jj];
            acc0 = fmaf(k, b.x, acc0);
            acc1 = fmaf(k, b.y, acc1);
            acc2 = fmaf(k, b.z, acc2);
            acc3 = fmaf(k, b.w, acc3);
        }
    }

    // dot with i charges (L1/L2 hit)
    const float a0 = g_q0[i0], a1 = g_q1[i0], a2 = g_q2[i0], a3 = g_q3[i0];
    float s = fmaf(a0, acc0, fmaf(a1, acc1, fmaf(a2, acc2, a3 * acc3)));
    if (!diag) s = s + s;
    else if (chunk == 0) {
        const float qq = fmaf(a0, a0, fmaf(a1, a1, fmaf(a2, a2, a3 * a3)));
        s = fmaf(SELF_RATIO, qq, s);
    }

    // deterministic in-block reduction (8 warps)
#pragma unroll
    for (int o = 16; o > 0; o >>= 1)
        s += __shfl_down_sync(0xffffffffu, s, o);

    __shared__ float red[TPB / 32];
    if ((t & 31) == 0) red[t >> 5] = s;
    __syncthreads();

    __shared__ bool is_last;
    if (t == 0) {
        g_partials[blockIdx.x] = ((red[0] + red[1]) + (red[2] + red[3]))
                               + ((red[4] + red[5]) + (red[6] + red[7]));
        __threadfence();
        const unsigned int c = atomicAdd(&g_count, 1u);
        is_last = (c == NBLK - 1);
    }
    __syncthreads();

    if (is_last) {
        __threadfence();
        double d = 0.0;
        for (int u = t; u < NBLK; u += TPB) d += (double)g_partials[u];

        __shared__ double rs[TPB];
        rs[t] = d;
        __syncthreads();
#pragma unroll
        for (int o = TPB / 2; o > 0; o >>= 1) {
            if (t < o) rs[t] += rs[t + o];
            __syncthreads();
        }
        if (t == 0) {
            const double INV_4PI = 0.07957747154594767;
            out[0] = (float)(rs[0] * INV_4PI);
            g_count = 0;   // reset for next graph replay
        }
    }
}

extern "C" void kernel_launch(void* const* d_in, const int* in_sizes, int n_in,
                              void* d_out, int out_size) {
    const float* pos = (const float*)d_in[0];   // [8192,3] fp32
    const float* q   = (const float*)d_in[1];   // [8192,4] fp32
    float* out = (float*)d_out;                 // [1] fp32

    bin_hist_kernel<<<NPTS / 256, 256>>>(pos);
    tot_kernel<<<NBINS / 256, 256>>>();
    scan_kernel<<<1, 256>>>();
    colstart_kernel<<<NBINS / 256, 256>>>();
    gather_kernel<<<NPTS / 256, 256>>>(pos, q);
    ewald_pair_kernel<<<NBLK, TPB>>>(out);
}

// round 12
// speedup vs baseline: 1.6233x; 1.2219x over previous
#include <cuda_runtime.h>
#include <cuda_bf16.h>

// Fixed shapes from reference setup_inputs
#define NPTS 8192
#define TPB  256
#define TILE 256                     // i-tile edge (1 i per thread)
#define JC   128                     // j-chunk per CTA
#define NTILES (NPTS / TILE)         // 32
#define NTRI (NTILES * (NTILES + 1) / 2)   // 528 triangular tiles
#define NBLK (NTRI * 2)              // 1056 CTAs

#define NBINS 4096                   // 12-bit Morton (4 bits/axis), 2.5-unit cells
#define NSB   32                     // superblocks of 256 points

// Sorted copies + metadata (no device allocation; fixed globals)
__device__ float g_sx[NPTS], g_sy[NPTS], g_sz[NPTS], g_ss[NPTS];
__device__ float g_q0[NPTS], g_q1[NPTS], g_q2[NPTS], g_q3[NPTS];
__device__ unsigned g_bin[NPTS];
__device__ unsigned g_bh[NBINS * NSB];      // bin-major histograms (self-cleaning)
__device__ unsigned g_tot[NBINS];
__device__ unsigned g_binstart[NBINS];
__device__ unsigned g_bstart[NBINS * NSB];
__device__ float g_partials[NBLK];
__device__ unsigned int g_count;            // zero at load; self-reset each launch

// A&S 7.1.25 (3-term, |eps| <= 2.5e-5), x = r/sqrt(2) folded into p
#define P3S  0.3326701f              // 0.47047 / sqrt(2)
#define A1c  0.3480242f
#define A2c  (-0.0958798f)
#define A3c  0.7478556f
#define NEG_HALF_LOG2E (-0.7213475204444817f)
#define SELF_RATIO 0.7978845608028654f   // (1/(2pi)^1.5) / (1/(4pi))
#define NEAR_R  3.0f                 // erfc(3/sqrt2) ~ 2.7e-3, incoherent -> safe
#define NEAR_R2 9.0f

__device__ __forceinline__ float rsqf(float a) {
    float r; asm("rsqrt.approx.f32 %0,%1;" : "=f"(r) : "f"(a)); return r;
}
__device__ __forceinline__ float rcpf(float a) {
    float r; asm("rcp.approx.f32 %0,%1;" : "=f"(r) : "f"(a)); return r;
}
__device__ __forceinline__ float exf(float a) {
    float r; asm("ex2.approx.f32 %0,%1;" : "=f"(r) : "f"(a)); return r;
}
// Full near-field kernel value erf(r/sqrt2)/r.
__device__ __forceinline__ float kern_corr(float r2, float rv) {
    const float r  = r2 * rv;
    const float tt = rcpf(fmaf(P3S, r, 1.0f));
    float h = fmaf(A3c, tt, A2c);
    h = fmaf(h, tt, A1c);
    const float u = (h * tt) * exf(r2 * NEG_HALF_LOG2E);
    return fmaf(-u, rv, rv);
}
// Correction delta: kern_corr(r2) - rv = -(poly*tt*ex)*rv  (-> 0 when far)
__device__ __forceinline__ float corr_delta(float r2, float rv) {
    const float r  = r2 * rv;
    const float tt = rcpf(fmaf(P3S, r, 1.0f));
    float h = fmaf(A3c, tt, A2c);
    h = fmaf(h, tt, A1c);
    const float u = (h * tt) * exf(r2 * NEG_HALF_LOG2E);
    return -u * rv;
}

// ---------- K1: Morton bin + bin-major histogram ----------
__device__ __forceinline__ unsigned spread4(unsigned v) {
    return (v & 1u) | ((v & 2u) << 2) | ((v & 4u) << 4) | ((v & 8u) << 6);
}
__global__ void bin_hist_kernel(const float* __restrict__ pos) {
    const int i = blockIdx.x * blockDim.x + threadIdx.x;
    const float x = pos[3 * i + 0];
    const float y = pos[3 * i + 1];
    const float z = pos[3 * i + 2];
    const unsigned ux = (unsigned)fminf(fmaxf((x + 20.f) * 0.4f, 0.f), 15.f);
    const unsigned uy = (unsigned)fminf(fmaxf((y + 20.f) * 0.4f, 0.f), 15.f);
    const unsigned uz = (unsigned)fminf(fmaxf((z + 20.f) * 0.4f, 0.f), 15.f);
    const unsigned b = (spread4(ux) << 2) | (spread4(uy) << 1) | spread4(uz);
    g_bin[i] = b;
    atomicAdd(&g_bh[b * NSB + (i >> 8)], 1u);    // counts: order-independent
    if (i == 0) g_count = 0;                      // belt & braces for replay
}

// ---------- K2: bin totals (4096 threads, batched uint4 reads) ----------
__global__ void tot_kernel() {
    const int b = blockIdx.x * blockDim.x + threadIdx.x;
    const uint4* p = (const uint4*)&g_bh[b * NSB];
    uint4 v[8];
#pragma unroll
    for (int k = 0; k < 8; k++) v[k] = p[k];      // 8 independent LDG.128
    unsigned s = 0;
#pragma unroll
    for (int k = 0; k < 8; k++) s += (v[k].x + v[k].y) + (v[k].z + v[k].w);
    g_tot[b] = s;
}

// ---------- K3: exclusive scan of 4096 totals (one small CTA) ----------
__global__ void scan_kernel() {
    const int t = threadIdx.x;           // 256 threads, 16 bins each
    const uint4* p = (const uint4*)&g_tot[t * 16];
    uint4 v[4];
#pragma unroll
    for (int k = 0; k < 4; k++) v[k] = p[k];      // batched loads
    unsigned loc[16], s = 0;
#pragma unroll
    for (int k = 0; k < 4; k++) {
        loc[4*k+0] = s; s += v[k].x;
        loc[4*k+1] = s; s += v[k].y;
        loc[4*k+2] = s; s += v[k].z;
        loc[4*k+3] = s; s += v[k].w;
    }
    __shared__ unsigned ts[256];
    ts[t] = s;
    __syncthreads();
    if (t == 0) {
        unsigned run = 0;
        for (int u = 0; u < 256; u++) { unsigned w = ts[u]; ts[u] = run; run += w; }
    }
    __syncthreads();
    const unsigned base = ts[t];
    unsigned outv[16];
#pragma unroll
    for (int k = 0; k < 16; k++) outv[k] = base + loc[k];
    uint4* po = (uint4*)&g_binstart[t * 16];
#pragma unroll
    for (int k = 0; k < 4; k++)
        po[k] = make_uint4(outv[4*k], outv[4*k+1], outv[4*k+2], outv[4*k+3]);
}

// ---------- K4: per-(bin,superblock) starts — register-staged, no aliasing ----------
__global__ void colstart_kernel() {
    const int b = blockIdx.x * blockDim.x + threadIdx.x;
    const uint4* p = (const uint4*)&g_bh[b * NSB];
    uint4 c[8];
#pragma unroll
    for (int k = 0; k < 8; k++) c[k] = p[k];      // ALL loads first (MLP=8)
    unsigned run = g_binstart[b];
    uint4 s[8];
#pragma unroll
    for (int k = 0; k < 8; k++) {
        s[k].x = run; run += c[k].x;
        s[k].y = run; run += c[k].y;
        s[k].z = run; run += c[k].z;
        s[k].w = run; run += c[k].w;
    }
    uint4* ps = (uint4*)&g_bstart[b * NSB];
    uint4* pc = (uint4*)&g_bh[b * NSB];
    const uint4 z = make_uint4(0u, 0u, 0u, 0u);
#pragma unroll
    for (int k = 0; k < 8; k++) { ps[k] = s[k]; pc[k] = z; }  // clean for replay
}

// ---------- K5: stable rank + gather into sorted SoA ----------
__global__ void gather_kernel(const float* __restrict__ pos, const float* __restrict__ q) {
    __shared__ unsigned sbin[256];
    const int t = threadIdx.x;
    const int i = blockIdx.x * 256 + t;
    const unsigned b = g_bin[i];
    sbin[t] = b;
    __syncthreads();
    unsigned off = 0;
#pragma unroll 8
    for (int j = 0; j < 256; j++)
        off += (sbin[j] == b) && (j < t);          // stable within superblock
    const unsigned r = g_bstart[b * NSB + blockIdx.x] + off;
    const float x = pos[3 * i + 0];
    const float y = pos[3 * i + 1];
    const float z = pos[3 * i + 2];
    g_sx[r] = x; g_sy[r] = y; g_sz[r] = z;
    g_ss[r] = fmaf(x, x, fmaf(y, y, z * z));
    g_q0[r] = q[4 * i + 0];
    g_q1[r] = q[4 * i + 1];
    g_q2[r] = q[4 * i + 2];
    g_q3[r] = q[4 * i + 3];
}

// ---------- Main pair kernel: mask-then-two-pass (unchanged from R11) ----------
__global__ void __launch_bounds__(TPB, 4)
ewald_pair_kernel(float* __restrict__ out) {
    __shared__ float4 sp[JC];   // {x, y, z, |p|^2}
    __shared__ float4 sb[JC];   // {b0, b1, b2, b3}

    const int t = threadIdx.x;
    const int lane = t & 31;
    const int tile  = blockIdx.x >> 1;
    const int chunk = blockIdx.x & 1;
    int I = 0, rem = tile;
    while (rem >= NTILES - I) { rem -= NTILES - I; I++; }
    const int J = I + rem;
    const bool diag = (I == J);

    const int jbase = J * TILE + chunk * JC;
    if (t < JC) {
        const int j = jbase + t;
        sp[t] = make_float4(g_sx[j], g_sy[j], g_sz[j], g_ss[j]);
    } else {
        const int tq = t - JC, j = jbase + tq;
        sb[tq] = make_float4(g_q0[j], g_q1[j], g_q2[j], g_q3[j]);
    }
    __syncthreads();

    const int i0 = I * TILE + t;
    const float xi = g_sx[i0], yi = g_sy[i0], zi = g_sz[i0];

    float acc0 = 0.f, acc1 = 0.f, acc2 = 0.f, acc3 = 0.f;

    if (!diag) {
        // --- warp i-blob bounding sphere (once) ---
        float mnx = xi, mxx = xi, mny = yi, mxy = yi, mnz = zi, mxz = zi;
#pragma unroll
        for (int o = 16; o > 0; o >>= 1) {
            mnx = fminf(mnx, __shfl_xor_sync(0xffffffffu, mnx, o));
            mxx = fmaxf(mxx, __shfl_xor_sync(0xffffffffu, mxx, o));
            mny = fminf(mny, __shfl_xor_sync(0xffffffffu, mny, o));
            mxy = fmaxf(mxy, __shfl_xor_sync(0xffffffffu, mxy, o));
            mnz = fminf(mnz, __shfl_xor_sync(0xffffffffu, mnz, o));
            mxz = fmaxf(mxz, __shfl_xor_sync(0xffffffffu, mxz, o));
        }
        const float cx = 0.5f * (mnx + mxx);
        const float cy = 0.5f * (mny + mxy);
        const float cz = 0.5f * (mnz + mxz);
        const float hx = 0.5f * (mxx - mnx);
        const float hy = 0.5f * (mxy - mny);
        const float hz = 0.5f * (mxz - mnz);
        const float Rb = sqrtf(fmaf(hx, hx, fmaf(hy, hy, hz * hz)));
        const float th = NEAR_R + Rb + 0.05f;
        const float th2 = th * th;

        // --- near masks: each lane tests j = lane + 32k ---
        unsigned mask[4];
#pragma unroll
        for (int k = 0; k < 4; k++) {
            const float4 p = sp[k * 32 + lane];
            const float dx = p.x - cx, dy = p.y - cy, dz = p.z - cz;
            const float d2 = fmaf(dx, dx, fmaf(dy, dy, dz * dz));
            mask[k] = __ballot_sync(0xffffffffu, d2 < th2);
        }

        // --- pass 1: branchless far path for all j ---
        const float nx2 = -2.f * xi, ny2 = -2.f * yi, nz2 = -2.f * zi;
        const float si  = g_ss[i0];
#pragma unroll 8
        for (int jj = 0; jj < JC; jj++) {
            const float4 p = sp[jj];
            const float r2 = fmaf(p.x, nx2, fmaf(p.y, ny2, fmaf(p.z, nz2, p.w + si)));
            const float rv = rsqf(r2);
            const float4 b = sb[jj];
            acc0 = fmaf(rv, b.x, acc0);
            acc1 = fmaf(rv, b.y, acc1);
            acc2 = fmaf(rv, b.z, acc2);
            acc3 = fmaf(rv, b.w, acc3);
        }

        // --- pass 2: erf correction only for near j (warp-uniform bit loop) ---
#pragma unroll
        for (int k = 0; k < 4; k++) {
            unsigned m = mask[k];
            while (m) {
                const int bit = __ffs(m) - 1;
                m &= m - 1u;
                const int jj = k * 32 + bit;
                const float4 p = sp[jj];
                const float r2 = fmaf(p.x, nx2, fmaf(p.y, ny2, fmaf(p.z, nz2, p.w + si)));
                const float rv = rsqf(r2);
                const float d  = corr_delta(r2, rv);   // ~0 for genuinely-far i
                const float4 b = sb[jj];
                acc0 = fmaf(d, b.x, acc0);
                acc1 = fmaf(d, b.y, acc1);
                acc2 = fmaf(d, b.z, acc2);
                acc3 = fmaf(d, b.w, acc3);
            }
        }
    } else {
        // diagonal tile: exact diff-form + per-iter vote (64 CTAs only)
#pragma unroll 8
        for (int jj = 0; jj < JC; jj++) {
            const float4 p = sp[jj];
            const float dx = p.x - xi;
            const float dy = p.y - yi;
            const float dz = p.z - zi;
            const float r2 = fmaf(dx, dx, fmaf(dy, dy, dz * dz));
            const float rv = rsqf(r2);
            float k = rv;
            if (__any_sync(0xffffffffu, r2 < NEAR_R2))
                k = kern_corr(r2, rv);
            k = (r2 > 0.f) ? k : 0.f;                   // exact-zero diagonal
            const float4 b = sb[jj];
            acc0 = fmaf(k, b.x, acc0);
            acc1 = fmaf(k, b.y, acc1);
            acc2 = fmaf(k, b.z, acc2);
            acc3 = fmaf(k, b.w, acc3);
        }
    }

    // dot with i charges (L1/L2 hit)
    const float a0 = g_q0[i0], a1 = g_q1[i0], a2 = g_q2[i0], a3 = g_q3[i0];
    float s = fmaf(a0, acc0, fmaf(a1, acc1, fmaf(a2, acc2, a3 * acc3)));
    if (!diag) s = s + s;
    else if (chunk == 0) {
        const float qq = fmaf(a0, a0, fmaf(a1, a1, fmaf(a2, a2, a3 * a3)));
        s = fmaf(SELF_RATIO, qq, s);
    }

    // deterministic in-block reduction (8 warps)
#pragma unroll
    for (int o = 16; o > 0; o >>= 1)
        s += __shfl_down_sync(0xffffffffu, s, o);

    __shared__ float red[TPB / 32];
    if ((t & 31) == 0) red[t >> 5] = s;
    __syncthreads();

    __shared__ bool is_last;
    if (t == 0) {
        g_partials[blockIdx.x] = ((red[0] + red[1]) + (red[2] + red[3]))
                               + ((red[4] + red[5]) + (red[6] + red[7]));
        __threadfence();
        const unsigned int c = atomicAdd(&g_count, 1u);
        is_last = (c == NBLK - 1);
    }
    __syncthreads();

    if (is_last) {
        __threadfence();
        double d = 0.0;
        for (int u = t; u < NBLK; u += TPB) d += (double)g_partials[u];

        __shared__ double rs[TPB];
        rs[t] = d;
        __syncthreads();
#pragma unroll
        for (int o = TPB / 2; o > 0; o >>= 1) {
            if (t < o) rs[t] += rs[t + o];
            __syncthreads();
        }
        if (t == 0) {
            const double INV_4PI = 0.07957747154594767;
            out[0] = (float)(rs[0] * INV_4PI);
            g_count = 0;   // reset for next graph replay
        }
    }
}

extern "C" void kernel_launch(void* const* d_in, const int* in_sizes, int n_in,
                              void* d_out, int out_size) {
    const float* pos = (const float*)d_in[0];   // [8192,3] fp32
    const float* q   = (const float*)d_in[1];   // [8192,4] fp32
    float* out = (float*)d_out;                 // [1] fp32

    bin_hist_kernel<<<NPTS / 256, 256>>>(pos);
    tot_kernel<<<NBINS / 256, 256>>>();
    scan_kernel<<<1, 256>>>();
    colstart_kernel<<<NBINS / 256, 256>>>();
    gather_kernel<<<NPTS / 256, 256>>>(pos, q);
    ewald_pair_kernel<<<NBLK, TPB>>>(out);
}

// round 13
// speedup vs baseline: 2.2492x; 1.3856x over previous
#include <cuda_runtime.h>
#include <cuda_bf16.h>

// Fixed shapes from reference setup_inputs
#define NPTS 8192
#define TPB  256
#define TILE 256                     // i-tile edge (1 i per thread)
#define JC   128                     // j-chunk per CTA
#define NTILES (NPTS / TILE)         // 32
#define NTRI (NTILES * (NTILES + 1) / 2)   // 528 triangular tiles
#define NBLK (NTRI * 2)              // 1056 CTAs

__device__ float g_partials[NBLK];
__device__ unsigned int g_count;     // zero at load; self-reset each launch

// A&S 7.1.25 (3-term, |eps| <= 2.5e-5), x = r/sqrt(2) folded into p
#define P3S  0.3326701f              // 0.47047 / sqrt(2)
#define A1c  0.3480242f
#define A2c  (-0.0958798f)
#define A3c  0.7478556f
#define NEG_HALF_LOG2E (-0.7213475204444817f)
#define SELF_RATIO 0.7978845608028654f   // (1/(2pi)^1.5) / (1/(4pi))
#define NEAR_R2 9.0f                 // erfc(3/sqrt2) ~ 2.7e-3, incoherent -> safe

__device__ __forceinline__ float rsqf(float a) {
    float r; asm("rsqrt.approx.f32 %0,%1;" : "=f"(r) : "f"(a)); return r;
}
__device__ __forceinline__ float rcpf(float a) {
    float r; asm("rcp.approx.f32 %0,%1;" : "=f"(r) : "f"(a)); return r;
}
__device__ __forceinline__ float exf(float a) {
    float r; asm("ex2.approx.f32 %0,%1;" : "=f"(r) : "f"(a)); return r;
}
// Full near-field kernel value erf(r/sqrt2)/r.
__device__ __forceinline__ float kern_corr(float r2, float rv) {
    const float r  = r2 * rv;
    const float tt = rcpf(fmaf(P3S, r, 1.0f));
    float h = fmaf(A3c, tt, A2c);
    h = fmaf(h, tt, A1c);
    const float u = (h * tt) * exf(r2 * NEG_HALF_LOG2E);
    return fmaf(-u, rv, rv);
}
// Correction delta: kern_corr(r2) - rv = -(poly*tt*ex)*rv  (-> 0 when far)
__device__ __forceinline__ float corr_delta(float r2, float rv) {
    const float r  = r2 * rv;
    const float tt = rcpf(fmaf(P3S, r, 1.0f));
    float h = fmaf(A3c, tt, A2c);
    h = fmaf(h, tt, A1c);
    const float u = (h * tt) * exf(r2 * NEG_HALF_LOG2E);
    return -u * rv;
}

// ---------- Single pair kernel: per-lane mask, two-pass, unsorted data ----------
__global__ void __launch_bounds__(TPB, 4)
ewald_pair_kernel(const float* __restrict__ pos, const float* __restrict__ q,
                  float* __restrict__ out) {
    __shared__ float4 sp[JC];   // {x, y, z, |p|^2}
    __shared__ float4 sb[JC];   // {b0, b1, b2, b3}

    const int t = threadIdx.x;
    const int tile  = blockIdx.x >> 1;
    const int chunk = blockIdx.x & 1;
    int I = 0, rem = tile;
    while (rem >= NTILES - I) { rem -= NTILES - I; I++; }
    const int J = I + rem;
    const bool diag = (I == J);

    const int jbase = J * TILE + chunk * JC;
    if (t < JC) {
        const int j = jbase + t;
        const float x = pos[3 * j + 0];
        const float y = pos[3 * j + 1];
        const float z = pos[3 * j + 2];
        sp[t] = make_float4(x, y, z, fmaf(x, x, fmaf(y, y, z * z)));
    } else {
        const int tq = t - JC;
        sb[tq] = ((const float4*)q)[jbase + tq];
    }
    __syncthreads();

    const int i0 = I * TILE + t;
    const float xi = pos[3 * i0 + 0];
    const float yi = pos[3 * i0 + 1];
    const float zi = pos[3 * i0 + 2];

    float acc0 = 0.f, acc1 = 0.f, acc2 = 0.f, acc3 = 0.f;

    if (!diag) {
        // dot-form r^2 = (si + sj) - 2 pi.pj
        const float nx2 = -2.f * xi, ny2 = -2.f * yi, nz2 = -2.f * zi;
        const float si  = fmaf(xi, xi, fmaf(yi, yi, zi * zi));

        // --- pass 1: branchless far path + per-lane near mask ---
        unsigned mask0 = 0u, mask1 = 0u, mask2 = 0u, mask3 = 0u;
#pragma unroll 8
        for (int jj = 0; jj < JC; jj++) {
            const float4 p = sp[jj];
            const float r2 = fmaf(p.x, nx2, fmaf(p.y, ny2, fmaf(p.z, nz2, p.w + si)));
            const float rv = rsqf(r2);
            const unsigned near = (r2 < NEAR_R2) ? 1u : 0u;
            if (jj < 32)       mask0 |= near << jj;
            else if (jj < 64)  mask1 |= near << (jj - 32);
            else if (jj < 96)  mask2 |= near << (jj - 64);
            else               mask3 |= near << (jj - 96);
            const float4 b = sb[jj];
            acc0 = fmaf(rv, b.x, acc0);
            acc1 = fmaf(rv, b.y, acc1);
            acc2 = fmaf(rv, b.z, acc2);
            acc3 = fmaf(rv, b.w, acc3);
        }

        // --- pass 2: erf correction only for this lane's near bits ---
        unsigned masks[4] = { mask0, mask1, mask2, mask3 };
#pragma unroll
        for (int k = 0; k < 4; k++) {
            unsigned m = masks[k];
            while (m) {                       // per-lane divergent, ~0-3 bits
                const int bit = __ffs(m) - 1;
                m &= m - 1u;
                const int jj = k * 32 + bit;
                const float4 p = sp[jj];
                const float r2 = fmaf(p.x, nx2, fmaf(p.y, ny2, fmaf(p.z, nz2, p.w + si)));
                const float rv = rsqf(r2);
                const float d  = corr_delta(r2, rv);
                const float4 b = sb[jj];
                acc0 = fmaf(d, b.x, acc0);
                acc1 = fmaf(d, b.y, acc1);
                acc2 = fmaf(d, b.z, acc2);
                acc3 = fmaf(d, b.w, acc3);
            }
        }
    } else {
        // diagonal tile: exact diff-form + vote (64 CTAs only)
#pragma unroll 8
        for (int jj = 0; jj < JC; jj++) {
            const float4 p = sp[jj];
            const float dx = p.x - xi;
            const float dy = p.y - yi;
            const float dz = p.z - zi;
            const float r2 = fmaf(dx, dx, fmaf(dy, dy, dz * dz));
            const float rv = rsqf(r2);
            float k = rv;
            if (__any_sync(0xffffffffu, r2 < NEAR_R2))
                k = kern_corr(r2, rv);
            k = (r2 > 0.f) ? k : 0.f;         // exact-zero diagonal
            const float4 b = sb[jj];
            acc0 = fmaf(k, b.x, acc0);
            acc1 = fmaf(k, b.y, acc1);
            acc2 = fmaf(k, b.z, acc2);
            acc3 = fmaf(k, b.w, acc3);
        }
    }

    // dot with i charges
    const float4 a = ((const float4*)q)[i0];
    float s = fmaf(a.x, acc0, fmaf(a.y, acc1, fmaf(a.z, acc2, a.w * acc3)));
    if (!diag) s = s + s;
    else if (chunk == 0) {
        const float qq = fmaf(a.x, a.x, fmaf(a.y, a.y, fmaf(a.z, a.z, a.w * a.w)));
        s = fmaf(SELF_RATIO, qq, s);
    }

    // deterministic in-block reduction (8 warps)
#pragma unroll
    for (int o = 16; o > 0; o >>= 1)
        s += __shfl_down_sync(0xffffffffu, s, o);

    __shared__ float red[TPB / 32];
    if ((t & 31) == 0) red[t >> 5] = s;
    __syncthreads();

    __shared__ bool is_last;
    if (t == 0) {
        g_partials[blockIdx.x] = ((red[0] + red[1]) + (red[2] + red[3]))
                               + ((red[4] + red[5]) + (red[6] + red[7]));
        __threadfence();
        const unsigned int c = atomicAdd(&g_count, 1u);
        is_last = (c == NBLK - 1);
    }
    __syncthreads();

    // last CTA: fixed-order fp64 final reduction + scale (order-independent of
    // which CTA runs it -> deterministic)
    if (is_last) {
        __threadfence();
        double d = 0.0;
        for (int u = t; u < NBLK; u += TPB) d += (double)g_partials[u];

        __shared__ double rs[TPB];
        rs[t] = d;
        __syncthreads();
#pragma unroll
        for (int o = TPB / 2; o > 0; o >>= 1) {
            if (t < o) rs[t] += rs[t + o];
            __syncthreads();
        }
        if (t == 0) {
            const double INV_4PI = 0.07957747154594767;
            out[0] = (float)(rs[0] * INV_4PI);
            g_count = 0;   // reset for next graph replay
        }
    }
}

extern "C" void kernel_launch(void* const* d_in, const int* in_sizes, int n_in,
                              void* d_out, int out_size) {
    const float* pos = (const float*)d_in[0];   // [8192,3] fp32
    const float* q   = (const float*)d_in[1];   // [8192,4] fp32
    float* out = (float*)d_out;                 // [1] fp32

    ewald_pair_kernel<<<NBLK, TPB>>>(pos, q, out);
}

// round 14
// speedup vs baseline: 2.8566x; 1.2700x over previous
#include <cuda_runtime.h>
#include <cuda_bf16.h>

// Fixed shapes from reference setup_inputs
#define NPTS 8192
#define TPB  256
#define TILE 256                     // i-tile edge (1 i per thread)
#define JC   128                     // j-chunk per CTA
#define NTILES (NPTS / TILE)         // 32
#define NTRI (NTILES * (NTILES + 1) / 2)   // 528 triangular tiles
#define NBLK (NTRI * 2)              // 1056 CTAs

__device__ float g_partials[NBLK];
__device__ unsigned int g_count;     // zero at load; self-reset each launch

// A&S 7.1.25 (3-term, |eps| <= 2.5e-5), x = r/sqrt(2) folded into p
#define P3S  0.3326701f              // 0.47047 / sqrt(2)
#define A1c  0.3480242f
#define A2c  (-0.0958798f)
#define A3c  0.7478556f
#define NEG_HALF_LOG2E (-0.7213475204444817f)
#define SELF_RATIO 0.7978845608028654f   // (1/(2pi)^1.5) / (1/(4pi))
#define NEAR_R2 9.0f                 // erfc(3/sqrt2) ~ 2.7e-3, incoherent -> safe

__device__ __forceinline__ float rsqf(float a) {
    float r; asm("rsqrt.approx.f32 %0,%1;" : "=f"(r) : "f"(a)); return r;
}
__device__ __forceinline__ float rcpf(float a) {
    float r; asm("rcp.approx.f32 %0,%1;" : "=f"(r) : "f"(a)); return r;
}
__device__ __forceinline__ float exf(float a) {
    float r; asm("ex2.approx.f32 %0,%1;" : "=f"(r) : "f"(a)); return r;
}
// Full near-field kernel value erf(r/sqrt2)/r.
__device__ __forceinline__ float kern_corr(float r2, float rv) {
    const float r  = r2 * rv;
    const float tt = rcpf(fmaf(P3S, r, 1.0f));
    float h = fmaf(A3c, tt, A2c);
    h = fmaf(h, tt, A1c);
    const float u = (h * tt) * exf(r2 * NEG_HALF_LOG2E);
    return fmaf(-u, rv, rv);
}
// Correction delta: kern_corr(r2) - rv = -(poly*tt*ex)*rv  (-> 0 when far)
__device__ __forceinline__ float corr_delta(float r2, float rv) {
    const float r  = r2 * rv;
    const float tt = rcpf(fmaf(P3S, r, 1.0f));
    float h = fmaf(A3c, tt, A2c);
    h = fmaf(h, tt, A1c);
    const float u = (h * tt) * exf(r2 * NEG_HALF_LOG2E);
    return -u * rv;
}

// ---------- Single pair kernel: per-lane mask (const-shift), two-pass ----------
__global__ void __launch_bounds__(TPB, 4)
ewald_pair_kernel(const float* __restrict__ pos, const float* __restrict__ q,
                  float* __restrict__ out) {
    __shared__ float4 sp[JC];   // {x, y, z, |p|^2}
    __shared__ float4 sb[JC];   // {b0, b1, b2, b3}

    const int t = threadIdx.x;
    const int tile  = blockIdx.x >> 1;
    const int chunk = blockIdx.x & 1;
    int I = 0, rem = tile;
    while (rem >= NTILES - I) { rem -= NTILES - I; I++; }
    const int J = I + rem;
    const bool diag = (I == J);

    const int jbase = J * TILE + chunk * JC;
    if (t < JC) {
        const int j = jbase + t;
        const float x = pos[3 * j + 0];
        const float y = pos[3 * j + 1];
        const float z = pos[3 * j + 2];
        sp[t] = make_float4(x, y, z, fmaf(x, x, fmaf(y, y, z * z)));
    } else {
        const int tq = t - JC;
        sb[tq] = ((const float4*)q)[jbase + tq];
    }
    __syncthreads();

    const int i0 = I * TILE + t;
    const float xi = pos[3 * i0 + 0];
    const float yi = pos[3 * i0 + 1];
    const float zi = pos[3 * i0 + 2];

    float acc0 = 0.f, acc1 = 0.f, acc2 = 0.f, acc3 = 0.f;

    if (!diag) {
        // dot-form r^2 = (si + sj) - 2 pi.pj
        const float nx2 = -2.f * xi, ny2 = -2.f * yi, nz2 = -2.f * zi;
        const float si  = fmaf(xi, xi, fmaf(yi, yi, zi * zi));

        // 4 words of 32 j each: pass 1 fully unrolled (const shifts),
        // pass 2 immediately on this word's register mask.
        for (int w = 0; w < 4; w++) {
            const int base = w * 32;
            unsigned m = 0u;
#pragma unroll
            for (int b = 0; b < 32; b++) {           // b is compile-time const
                const float4 p = sp[base + b];
                const float r2 = fmaf(p.x, nx2, fmaf(p.y, ny2, fmaf(p.z, nz2, p.w + si)));
                const float rv = rsqf(r2);
                m |= (r2 < NEAR_R2) ? (1u << b) : 0u;   // one LOP, const shift
                const float4 c = sb[base + b];
                acc0 = fmaf(rv, c.x, acc0);
                acc1 = fmaf(rv, c.y, acc1);
                acc2 = fmaf(rv, c.z, acc2);
                acc3 = fmaf(rv, c.w, acc3);
            }
            while (m) {                   // per-lane divergent, ~0-2 bits/word
                const int bit = __ffs(m) - 1;
                m &= m - 1u;
                const int jj = base + bit;
                const float4 p = sp[jj];
                const float r2 = fmaf(p.x, nx2, fmaf(p.y, ny2, fmaf(p.z, nz2, p.w + si)));
                const float rv = rsqf(r2);
                const float d  = corr_delta(r2, rv);
                const float4 c = sb[jj];
                acc0 = fmaf(d, c.x, acc0);
                acc1 = fmaf(d, c.y, acc1);
                acc2 = fmaf(d, c.z, acc2);
                acc3 = fmaf(d, c.w, acc3);
            }
        }
    } else {
        // diagonal tile: exact diff-form + vote (64 CTAs only)
#pragma unroll 8
        for (int jj = 0; jj < JC; jj++) {
            const float4 p = sp[jj];
            const float dx = p.x - xi;
            const float dy = p.y - yi;
            const float dz = p.z - zi;
            const float r2 = fmaf(dx, dx, fmaf(dy, dy, dz * dz));
            const float rv = rsqf(r2);
            float k = rv;
            if (__any_sync(0xffffffffu, r2 < NEAR_R2))
                k = kern_corr(r2, rv);
            k = (r2 > 0.f) ? k : 0.f;         // exact-zero diagonal
            const float4 b = sb[jj];
            acc0 = fmaf(k, b.x, acc0);
            acc1 = fmaf(k, b.y, acc1);
            acc2 = fmaf(k, b.z, acc2);
            acc3 = fmaf(k, b.w, acc3);
        }
    }

    // dot with i charges
    const float4 a = ((const float4*)q)[i0];
    float s = fmaf(a.x, acc0, fmaf(a.y, acc1, fmaf(a.z, acc2, a.w * acc3)));
    if (!diag) s = s + s;
    else if (chunk == 0) {
        const float qq = fmaf(a.x, a.x, fmaf(a.y, a.y, fmaf(a.z, a.z, a.w * a.w)));
        s = fmaf(SELF_RATIO, qq, s);
    }

    // deterministic in-block reduction (8 warps)
#pragma unroll
    for (int o = 16; o > 0; o >>= 1)
        s += __shfl_down_sync(0xffffffffu, s, o);

    __shared__ float red[TPB / 32];
    if ((t & 31) == 0) red[t >> 5] = s;
    __syncthreads();

    __shared__ bool is_last;
    if (t == 0) {
        g_partials[blockIdx.x] = ((red[0] + red[1]) + (red[2] + red[3]))
                               + ((red[4] + red[5]) + (red[6] + red[7]));
        __threadfence();
        const unsigned int c = atomicAdd(&g_count, 1u);
        is_last = (c == NBLK - 1);
    }
    __syncthreads();

    // last CTA: fixed-order fp64 final reduction + scale
    if (is_last) {
        __threadfence();
        double d = 0.0;
        for (int u = t; u < NBLK; u += TPB) d += (double)g_partials[u];

        __shared__ double rs[TPB];
        rs[t] = d;
        __syncthreads();
#pragma unroll
        for (int o = TPB / 2; o > 0; o >>= 1) {
            if (t < o) rs[t] += rs[t + o];
            __syncthreads();
        }
        if (t == 0) {
            const double INV_4PI = 0.07957747154594767;
            out[0] = (float)(rs[0] * INV_4PI);
            g_count = 0;   // reset for next graph replay
        }
    }
}

extern "C" void kernel_launch(void* const* d_in, const int* in_sizes, int n_in,
                              void* d_out, int out_size) {
    const float* pos = (const float*)d_in[0];   // [8192,3] fp32
    const float* q   = (const float*)d_in[1];   // [8192,4] fp32
    float* out = (float*)d_out;                 // [1] fp32

    ewald_pair_kernel<<<NBLK, TPB>>>(pos, q, out);
}